// round 15
// baseline (speedup 1.0000x reference)
#include <cuda_runtime.h>

#define EPSV 1e-5f

// ---- scratch (__device__ globals) ----
__device__ float g_z1p[32*16*8*256];   // conv1 partials (32 chunks)
__device__ float g_z1[16*8*256];       // conv1 out (residual base)
__device__ float g_cm[128];            // per (b,c) GN mean
__device__ float g_cr[128];            // per (b,c) GN rstd
__device__ float4 g_p4[512*256];       // attn partials (den, a0, a1, -)
__device__ float g_z3[16*8*256];       // post-MLP (pre-GN2)
__device__ float g_gs[128*16];         // GN2 partial sums
__device__ __align__(16) float g_kw[320*288];  // collapsed 6x6 weights [o][c][36]

__device__ __forceinline__ float siluf(float x){
    return __fdividef(x, 1.0f+__expf(-x));
}

// packed f32x2 helpers (sm_103a FFMA2)
__device__ __forceinline__ void ffma2(unsigned long long& d, unsigned long long a, unsigned long long b){
    asm("fma.rn.f32x2 %0, %1, %2, %0;" : "+l"(d) : "l"(a), "l"(b));
}
__device__ __forceinline__ unsigned long long pk2(float lo, float hi){
    unsigned long long r; asm("mov.b64 %0, {%1,%2};" : "=l"(r) : "f"(lo), "f"(hi)); return r;
}
__device__ __forceinline__ void upk2(float& lo, float& hi, unsigned long long v){
    asm("mov.b64 {%0,%1}, %2;" : "=f"(lo), "=f"(hi) : "l"(v));
}

// ---- K0: collapse 3x3 conv2 weights into 6x6 stride-4 transposed-conv kernel ----
__global__ void k_wt(const float* __restrict__ w2){
    int idx = blockIdx.x*256+threadIdx.x;      // 92160 = 320*8*36
    if(idx>=92160) return;
    int o = idx/288, r = idx-o*288, c = r/36, q = r-c*36, ky = q/6, kx = q-ky*6;
    int dy0 = max(0, 2-ky), dy1 = min(2, 5-ky);
    int dx0 = max(0, 2-kx), dx1 = min(2, 5-kx);
    float s=0.f;
    for(int dy=dy0;dy<=dy1;dy++)
        for(int dx=dx0;dx<=dx1;dx++)
            s += w2[o*72 + c*9 + dy*3 + dx];
    g_kw[idx] = s;
}

// ---- K1: fused 4x4 pool + GN1(32) stats + SiLU + conv1 (320->8 partials), 256 thr ----
__global__ void __launch_bounds__(256) k_pconv1(const float* __restrict__ x,
                                                const float* __restrict__ g1,
                                                const float* __restrict__ b1,
                                                const float* __restrict__ w1){
    __shared__ float sp[10*324];                 // padded planes
    __shared__ __align__(16) float sw[10*72];    // [ci][k][o]
    __shared__ float2 sb[8];
    int j = blockIdx.x, b = blockIdx.y;
    int t = threadIdx.x;
    int Y = t>>4, X = t&15;
    // weight staging LDGs first so they overlap the pooling reads
    for(int i=t;i<720;i+=256){
        int ci = i/72, r = i-ci*72, k = r>>3, o = r&7;
        sw[i] = w1[o*2880 + (j*10+ci)*9 + k];
    }
    // pool 10 channels, pairs batched
    float pv[10];
    float s=0.f, s2=0.f;
    #pragma unroll
    for(int cp=0;cp<5;cp++){
        const float4* xr0 = (const float4*)(x + (size_t)(b*320 + j*10 + 2*cp    )*4096);
        const float4* xr1 = (const float4*)(x + (size_t)(b*320 + j*10 + 2*cp + 1)*4096);
        float4 v0[4], v1[4];
        #pragma unroll
        for(int r=0;r<4;r++) v0[r] = xr0[(4*Y+r)*16 + X];
        #pragma unroll
        for(int r=0;r<4;r++) v1[r] = xr1[(4*Y+r)*16 + X];
        float a0=0.f, a1=0.f;
        #pragma unroll
        for(int r=0;r<4;r++) a0 += v0[r].x+v0[r].y+v0[r].z+v0[r].w;
        #pragma unroll
        for(int r=0;r<4;r++) a1 += v1[r].x+v1[r].y+v1[r].z+v1[r].w;
        a0 *= (1.0f/16.0f); a1 *= (1.0f/16.0f);
        pv[2*cp]=a0; pv[2*cp+1]=a1;
        s += a0+a1; s2 += a0*a0 + a1*a1;
    }
    // zero sp borders
    for(int i=t;i<3240;i+=256){
        int p = i%324, r18 = p/18, c18 = p-r18*18;
        if(r18==0||r18==17||c18==0||c18==17) sp[i]=0.f;
    }
    #pragma unroll
    for(int o=16;o;o>>=1){
        s  += __shfl_xor_sync(0xffffffffu, s,  o);
        s2 += __shfl_xor_sync(0xffffffffu, s2, o);
    }
    if((t&31)==0) sb[t>>5] = make_float2(s,s2);
    __syncthreads();
    float P=0.f,Q=0.f;
    #pragma unroll
    for(int w=0;w<8;w++){ P+=sb[w].x; Q+=sb[w].y; }
    float m  = P*(1.0f/2560.0f);
    float rs = rsqrtf(Q*(1.0f/2560.0f)-m*m+EPSV);
    #pragma unroll
    for(int ci=0;ci<10;ci++){
        int c = j*10+ci;
        sp[ci*324 + (Y+1)*18 + (X+1)] = siluf((pv[ci]-m)*rs*g1[c] + b1[c]);
    }
    __syncthreads();
    float acc[8];
    #pragma unroll
    for(int o=0;o<8;o++) acc[o]=0.f;
    #pragma unroll
    for(int ci=0;ci<10;ci++){
        float a[9];
        #pragma unroll
        for(int dy=0;dy<3;dy++)
            #pragma unroll
            for(int dx=0;dx<3;dx++)
                a[dy*3+dx] = sp[ci*324 + (Y+dy)*18 + (X+dx)];
        #pragma unroll
        for(int k=0;k<9;k++){
            float av = a[k];
            float4 wA = *(const float4*)&sw[((ci*9+k)<<3)];
            float4 wB = *(const float4*)&sw[((ci*9+k)<<3)+4];
            acc[0]+=av*wA.x; acc[1]+=av*wA.y; acc[2]+=av*wA.z; acc[3]+=av*wA.w;
            acc[4]+=av*wB.x; acc[5]+=av*wB.y; acc[6]+=av*wB.z; acc[7]+=av*wB.w;
        }
    }
    #pragma unroll
    for(int o=0;o<8;o++)
        g_z1p[(((j*16+b)*8+o)<<8) + t] = acc[o];
}

// ---- K2: merge partials + bias; per-channel GN stats ----
__global__ void k_merge(const float* __restrict__ bc1){
    __shared__ float2 sb[8];
    int bc = blockIdx.x;               // b*8 + c
    int b = bc>>3, c = bc&7;
    int t = threadIdx.x;
    float s = bc1[c];
    #pragma unroll
    for(int jj=0;jj<32;jj++)
        s += g_z1p[(((jj*16+b)*8+c)<<8) + t];
    g_z1[bc*256 + t] = s;
    float p = s, q = s*s;
    #pragma unroll
    for(int o=16;o;o>>=1){
        p += __shfl_xor_sync(0xffffffffu, p, o);
        q += __shfl_xor_sync(0xffffffffu, q, o);
    }
    if((t&31)==0) sb[t>>5] = make_float2(p,q);
    __syncthreads();
    if(t==0){
        float P=0.f,Q=0.f;
        #pragma unroll
        for(int w=0;w<8;w++){ P+=sb[w].x; Q+=sb[w].y; }
        float m = P*(1.f/256.f);
        g_cm[bc]=m;
        g_cr[bc]=rsqrtf(Q*(1.f/256.f)-m*m+EPSV);
    }
}

// ---- K3: GN-apply + qkv + split-K attention partials; block=(b,h,chunk of 8) ----
__global__ void __launch_bounds__(256) k_attn(const float* __restrict__ ga,
                                              const float* __restrict__ ba,
                                              const float* __restrict__ wq,
                                              const float* __restrict__ bq){
    __shared__ float2 sk[256], sv[256];
    __shared__ float swq[192];
    int blk = blockIdx.x;              // b*32 + h*8 + chunk
    int b = blk>>5, h = (blk>>3)&3, ch = blk&7;
    int t = threadIdx.x;               // row
    if(t<192) swq[t] = wq[t];
    __syncthreads();
    float nv[8];
    #pragma unroll
    for(int c=0;c<8;c++){
        int bc = b*8+c;
        float z = g_z1[bc*256+t];
        nv[c] = (z-g_cm[bc])*g_cr[bc]*ga[c] + ba[c];
    }
    float q0=bq[2*h], q1=bq[2*h+1];
    float k0=bq[8+2*h], k1=bq[9+2*h];
    float v0=bq[16+2*h], v1=bq[17+2*h];
    #pragma unroll
    for(int c=0;c<8;c++){
        q0 += swq[(2*h  )*8+c]*nv[c];
        q1 += swq[(2*h+1)*8+c]*nv[c];
        k0 += swq[(8+2*h)*8+c]*nv[c];
        k1 += swq[(9+2*h)*8+c]*nv[c];
        v0 += swq[(16+2*h)*8+c]*nv[c];
        v1 += swq[(17+2*h)*8+c]*nv[c];
    }
    sk[t] = make_float2(k0,k1);
    sv[t] = make_float2(v0,v1);
    const float scale = 0.7071067811865475f;
    q0*=scale; q1*=scale;
    __syncthreads();
    float den=0.f, a0=0.f, a1=0.f;
    int m0 = ch*32;
    #pragma unroll 8
    for(int m=m0;m<m0+32;m++){          // broadcast LDS
        float2 kk = sk[m];
        float e = __expf(q0*kk.x + q1*kk.y);
        float2 vv = sv[m];
        den += e;
        a0 += e*vv.x; a1 += e*vv.y;
    }
    g_p4[blk*256 + t] = make_float4(den, a0, a1, 0.f);
}

// ---- K4: combine attn + proj+res + LN + MLP(gelu) + res -> z3 + GN2 partials ----
__global__ void __launch_bounds__(128) k_mlp(
        const float* __restrict__ wp, const float* __restrict__ bp,
        const float* __restrict__ lng, const float* __restrict__ lnb,
        const float* __restrict__ wf1, const float* __restrict__ bf1,
        const float* __restrict__ wf2, const float* __restrict__ bf2){
    __shared__ float sred[16*4];
    int b = blockIdx.x, chunk = blockIdx.y, t = threadIdx.x;
    int p = chunk*32 + (t>>2), sub = t&3;      // pixel, head-lane
    float den=0.f, s0=0.f, s1=0.f;
    #pragma unroll
    for(int ch=0;ch<8;ch++){
        float4 v = g_p4[((b*32 + sub*8 + ch)<<8) + p];
        den += v.x; s0 += v.y; s1 += v.z;
    }
    float inv = __fdividef(1.0f, den);
    float aoh0 = s0*inv, aoh1 = s1*inv;
    float ao[8];
    #pragma unroll
    for(int h=0;h<4;h++){
        ao[2*h]   = __shfl_sync(0xffffffffu, aoh0, h, 4);
        ao[2*h+1] = __shfl_sync(0xffffffffu, aoh1, h, 4);
    }
    float z2[8];
    #pragma unroll
    for(int c=0;c<8;c++){
        float s = bp[c] + g_z1[(b*8+c)*256+p];
        #pragma unroll
        for(int d=0;d<8;d++) s += wp[c*8+d]*ao[d];
        z2[c]=s;
    }
    float mu=0.f;
    #pragma unroll
    for(int c=0;c<8;c++) mu += z2[c];
    mu *= 0.125f;
    float var=0.f;
    #pragma unroll
    for(int c=0;c<8;c++){ float d=z2[c]-mu; var += d*d; }
    float rsl = rsqrtf(var*0.125f + EPSV);
    float ln[8];
    #pragma unroll
    for(int c=0;c<8;c++) ln[c] = (z2[c]-mu)*rsl*lng[c] + lnb[c];
    float hg[4];
    #pragma unroll
    for(int u=0;u<4;u++){
        int jj = sub*4+u;
        float s = bf1[jj];
        #pragma unroll
        for(int c=0;c<8;c++) s += wf1[jj*8+c]*ln[c];
        hg[u] = 0.5f*s*(1.0f + erff(s*0.7071067811865475f));
    }
    float z3[8];
    #pragma unroll
    for(int c=0;c<8;c++){
        float s = 0.f;
        #pragma unroll
        for(int u=0;u<4;u++) s += wf2[c*16 + sub*4+u]*hg[u];
        s += __shfl_xor_sync(0xffffffffu, s, 1);
        s += __shfl_xor_sync(0xffffffffu, s, 2);
        z3[c] = z2[c] + bf2[c] + s;
    }
    if(sub==0){
        #pragma unroll
        for(int c=0;c<8;c++) g_z3[(b*8+c)*256+p] = z3[c];
    }
    float red[16];
    #pragma unroll
    for(int c=0;c<8;c++){ red[c]=z3[c]; red[8+c]=z3[c]*z3[c]; }
    #pragma unroll
    for(int q=0;q<16;q++)
        #pragma unroll
        for(int o=16;o;o>>=1) red[q] += __shfl_xor_sync(0xffffffffu, red[q], o);
    if((t&31)==0){
        #pragma unroll
        for(int q=0;q<16;q++) sred[q*4 + (t>>5)] = red[q];
    }
    __syncthreads();
    if(t<16){
        float tot = sred[t*4]+sred[t*4+1]+sred[t*4+2]+sred[t*4+3];
        g_gs[(b*8+chunk)*16 + t] = tot;   // 4x each pixel -> /1024 later
    }
}

// ---- K5: GN2 + SiLU staging + upsample+conv2 (8->320), low-reg FFMA2 ----
// per-row macro: load 5 overlapping packed pairs from an aligned smem row
#define LOADROW(r) { \
    const unsigned long long* sar = (const unsigned long long*)&sa[(c*18 + Yq + (r))*18 + 4*Xs]; \
    ap[0]=sar[0]; ap[2]=sar[1]; ap[4]=sar[2]; \
    float a0_,a1_,a2_,a3_,a4_,a5_; \
    upk2(a0_,a1_,ap[0]); upk2(a2_,a3_,ap[2]); upk2(a4_,a5_,ap[4]); \
    ap[1]=pk2(a1_,a2_); ap[3]=pk2(a3_,a4_); }

// kx routing: kx0:(xl=3,scb=2) kx1:(0,1) kx2:(1,1) kx3:(2,1) kx4:(3,1) kx5:(0,0)
#define DOKY(ky, ry) { \
    const ulonglong2* wp2 = (const ulonglong2*)(wc + (ky)*6); \
    ulonglong2 wA=wp2[0], wB=wp2[1], wC=wp2[2]; \
    ffma2(acc2[((ry)*4+3)*2+0], wA.x, ap[2]); ffma2(acc2[((ry)*4+3)*2+1], wA.x, ap[4]); \
    ffma2(acc2[((ry)*4+0)*2+0], wA.y, ap[1]); ffma2(acc2[((ry)*4+0)*2+1], wA.y, ap[3]); \
    ffma2(acc2[((ry)*4+1)*2+0], wB.x, ap[1]); ffma2(acc2[((ry)*4+1)*2+1], wB.x, ap[3]); \
    ffma2(acc2[((ry)*4+2)*2+0], wB.y, ap[1]); ffma2(acc2[((ry)*4+2)*2+1], wB.y, ap[3]); \
    ffma2(acc2[((ry)*4+3)*2+0], wC.x, ap[1]); ffma2(acc2[((ry)*4+3)*2+1], wC.x, ap[3]); \
    ffma2(acc2[((ry)*4+0)*2+0], wC.y, ap[0]); ffma2(acc2[((ry)*4+0)*2+1], wC.y, ap[2]); }

__global__ void __launch_bounds__(256) k_conv2(const float* __restrict__ bc2,
                                               const float* __restrict__ g2,
                                               const float* __restrict__ b2,
                                               float* __restrict__ out){
    __shared__ __align__(16) float sa[2592];                 // padded silu(gn2) planes
    __shared__ __align__(16) unsigned long long sw2[1152];   // weights pre-packed (w,w)
    __shared__ float sst[16];
    int og = blockIdx.x, b = blockIdx.y;
    int t = threadIdx.x;
    {
        float4 z4 = make_float4(0.f,0.f,0.f,0.f);
        float4* sa4 = (float4*)sa;
        for(int i=t;i<648;i+=256) sa4[i] = z4;
    }
    {   // weights: vector load + duplicate-pack
        const float2* kw2 = (const float2*)(g_kw + og*1152);
        for(int i=t;i<576;i+=256){
            float2 v = kw2[i];
            sw2[2*i]   = pk2(v.x, v.x);
            sw2[2*i+1] = pk2(v.y, v.y);
        }
    }
    if(t<16){
        float tot=0.f;
        #pragma unroll
        for(int k=0;k<8;k++) tot += g_gs[(b*8+k)*16 + t];
        sst[t]=tot;
    }
    __syncthreads();
    {
        int Y=t>>4, X=t&15;
        #pragma unroll
        for(int c=0;c<8;c++){
            float m  = sst[c]*(1.f/1024.f);
            float rs = rsqrtf(sst[8+c]*(1.f/1024.f)-m*m+EPSV);
            float v = g_z3[(b*8+c)*256 + t];
            sa[c*324 + (Y+1)*18 + (X+1)] = siluf((v-m)*rs*g2[c] + b2[c]);
        }
    }
    __syncthreads();
    int ol = t>>6, u = t&63, Yq = u>>2, Xs = u&3;
    int o = og*4+ol;
    float bias = bc2[o];
    unsigned long long acc2[32];    // [(ry*4+xl0)*2+p]: lo->col xl0+8p, hi->col xl0+8p+4
    unsigned long long bias2 = pk2(bias, bias);
    #pragma unroll
    for(int i=0;i<32;i++) acc2[i]=bias2;
    #pragma unroll
    for(int c=0;c<8;c++){
        const unsigned long long* wc = &sw2[(ol*8 + c)*36];
        unsigned long long ap[5];
        // riw=2 serves ky=0 (ry=3)
        LOADROW(2);
        DOKY(0,3);
        // riw=1 serves ky=1..4 (ry=0,1,2,3)
        LOADROW(1);
        DOKY(1,0); DOKY(2,1); DOKY(3,2); DOKY(4,3);
        // riw=0 serves ky=5 (ry=0)
        LOADROW(0);
        DOKY(5,0);
    }
    float accs[64];
    #pragma unroll
    for(int ry=0;ry<4;ry++)
        #pragma unroll
        for(int xl0=0;xl0<4;xl0++)
            #pragma unroll
            for(int p=0;p<2;p++){
                float lo,hi;
                upk2(lo,hi, acc2[(ry*4+xl0)*2+p]);
                accs[ry*16 + 8*p + xl0]     = lo;
                accs[ry*16 + 8*p + 4 + xl0] = hi;
            }
    float4* ob = (float4*)(out + ((size_t)(b*320 + o)*64 + 4*Yq)*64 + 16*Xs);
    #pragma unroll
    for(int ry=0;ry<4;ry++)
        #pragma unroll
        for(int j=0;j<4;j++)
            ob[ry*16 + j] = make_float4(accs[ry*16+j*4], accs[ry*16+j*4+1],
                                        accs[ry*16+j*4+2], accs[ry*16+j*4+3]);
}

extern "C" void kernel_launch(void* const* d_in, const int* in_sizes, int n_in,
                              void* d_out, int out_size) {
    const float* x   = (const float*)d_in[0];
    const float* g1  = (const float*)d_in[1];
    const float* b1  = (const float*)d_in[2];
    const float* w1  = (const float*)d_in[3];
    const float* bc1 = (const float*)d_in[4];
    const float* ga  = (const float*)d_in[5];
    const float* ba  = (const float*)d_in[6];
    const float* wq  = (const float*)d_in[7];
    const float* bq  = (const float*)d_in[8];
    const float* wp  = (const float*)d_in[9];
    const float* bp  = (const float*)d_in[10];
    const float* lng = (const float*)d_in[11];
    const float* lnb = (const float*)d_in[12];
    const float* wf1 = (const float*)d_in[13];
    const float* bf1 = (const float*)d_in[14];
    const float* wf2 = (const float*)d_in[15];
    const float* bf2 = (const float*)d_in[16];
    const float* g2  = (const float*)d_in[17];
    const float* b2  = (const float*)d_in[18];
    const float* w2  = (const float*)d_in[19];
    const float* bc2 = (const float*)d_in[20];
    float* out = (float*)d_out;

    k_wt    <<<360, 256>>>(w2);
    k_pconv1<<<dim3(32,16), 256>>>(x, g1, b1, w1);
    k_merge <<<128, 256>>>(bc1);
    k_attn  <<<512, 256>>>(ga, ba, wq, bq);
    k_mlp   <<<dim3(16,8), 128>>>(wp, bp, lng, lnb, wf1, bf1, wf2, bf2);
    k_conv2 <<<dim3(80,16), 256>>>(bc2, g2, b2, out);
}

// round 16
// speedup vs baseline: 1.1081x; 1.1081x over previous
#include <cuda_runtime.h>

#define EPSV 1e-5f

// ---- scratch (__device__ globals) ----
__device__ float g_z1p[32*16*8*256];   // conv1 partials (32 chunks)
__device__ float g_z1[16*8*256];       // conv1 out (residual base)
__device__ float g_cm[128];            // per (b,c) GN mean
__device__ float g_cr[128];            // per (b,c) GN rstd
__device__ float4 g_p4[512*256];       // attn partials (den, a0, a1, -)
__device__ float g_z3[16*8*256];       // post-MLP (pre-GN2)
__device__ float g_gs[128*16];         // GN2 partial sums
__device__ __align__(16) float g_kw[320*288];  // collapsed 6x6 weights [o][c][36]

__device__ __forceinline__ float siluf(float x){
    return __fdividef(x, 1.0f+__expf(-x));
}

// ---- K1: fused 4x4 pool + GN1(32) stats + SiLU + conv1 (320->8 partials)
//      + conv2-weight collapse epilogue (1 elem/thread, hidden under latency) ----
__global__ void __launch_bounds__(256) k_pconv1(const float* __restrict__ x,
                                                const float* __restrict__ g1,
                                                const float* __restrict__ b1,
                                                const float* __restrict__ w1,
                                                const float* __restrict__ w2){
    __shared__ float sp[10*324];                 // padded planes
    __shared__ __align__(16) float sw[10*72];    // [ci][k][o]
    __shared__ float2 sb[8];
    int j = blockIdx.x, b = blockIdx.y;
    int t = threadIdx.x;
    int Y = t>>4, X = t&15;
    // conv2 weight collapse: one element per thread (independent work,
    // overlaps this kernel's memory stalls; consumed 4 launches later)
    {
        int idx = (b*32 + j)*256 + t + ((b*32+j)>=352 ? -1 : 0); // 512*256 = 131072 > 92160
        idx = (b*32 + j)*256 + t;
        if(idx < 92160){
            int o = idx/288, r = idx-o*288, c = r/36, q = r-c*36, ky = q/6, kx = q-ky*6;
            int dy0 = max(0, 2-ky), dy1 = min(2, 5-ky);
            int dx0 = max(0, 2-kx), dx1 = min(2, 5-kx);
            float s=0.f;
            for(int dy=dy0;dy<=dy1;dy++)
                for(int dx=dx0;dx<=dx1;dx++)
                    s += w2[o*72 + c*9 + dy*3 + dx];
            g_kw[idx] = s;
        }
    }
    // weight staging LDGs (overlap pooling reads)
    for(int i=t;i<720;i+=256){
        int ci = i/72, r = i-ci*72, k = r>>3, o = r&7;
        sw[i] = w1[o*2880 + (j*10+ci)*9 + k];
    }
    // pool 10 channels
    float pv[10];
    float s=0.f, s2=0.f;
    #pragma unroll
    for(int ci=0;ci<10;ci++){
        const float4* xr = (const float4*)(x + (size_t)(b*320 + j*10 + ci)*4096);
        float a = 0.f;
        #pragma unroll
        for(int r=0;r<4;r++){
            float4 v = xr[(4*Y+r)*16 + X];
            a += v.x+v.y+v.z+v.w;
        }
        a *= (1.0f/16.0f);
        pv[ci]=a; s+=a; s2+=a*a;
    }
    // zero sp borders
    for(int i=t;i<3240;i+=256){
        int p = i%324, r18 = p/18, c18 = p-r18*18;
        if(r18==0||r18==17||c18==0||c18==17) sp[i]=0.f;
    }
    #pragma unroll
    for(int o=16;o;o>>=1){
        s  += __shfl_xor_sync(0xffffffffu, s,  o);
        s2 += __shfl_xor_sync(0xffffffffu, s2, o);
    }
    if((t&31)==0) sb[t>>5] = make_float2(s,s2);
    __syncthreads();
    float P=0.f,Q=0.f;
    #pragma unroll
    for(int w=0;w<8;w++){ P+=sb[w].x; Q+=sb[w].y; }
    float m  = P*(1.0f/2560.0f);
    float rs = rsqrtf(Q*(1.0f/2560.0f)-m*m+EPSV);
    #pragma unroll
    for(int ci=0;ci<10;ci++){
        int c = j*10+ci;
        sp[ci*324 + (Y+1)*18 + (X+1)] = siluf((pv[ci]-m)*rs*g1[c] + b1[c]);
    }
    __syncthreads();
    float acc[8];
    #pragma unroll
    for(int o=0;o<8;o++) acc[o]=0.f;
    #pragma unroll
    for(int ci=0;ci<10;ci++){
        float a[9];
        #pragma unroll
        for(int dy=0;dy<3;dy++)
            #pragma unroll
            for(int dx=0;dx<3;dx++)
                a[dy*3+dx] = sp[ci*324 + (Y+dy)*18 + (X+dx)];
        #pragma unroll
        for(int k=0;k<9;k++){
            float av = a[k];
            float4 wA = *(const float4*)&sw[((ci*9+k)<<3)];
            float4 wB = *(const float4*)&sw[((ci*9+k)<<3)+4];
            acc[0]+=av*wA.x; acc[1]+=av*wA.y; acc[2]+=av*wA.z; acc[3]+=av*wA.w;
            acc[4]+=av*wB.x; acc[5]+=av*wB.y; acc[6]+=av*wB.z; acc[7]+=av*wB.w;
        }
    }
    #pragma unroll
    for(int o=0;o<8;o++)
        g_z1p[(((j*16+b)*8+o)<<8) + t] = acc[o];
}

// ---- K2: merge partials + bias; per-channel GN stats ----
__global__ void k_merge(const float* __restrict__ bc1){
    __shared__ float2 sb[8];
    int bc = blockIdx.x;               // b*8 + c
    int b = bc>>3, c = bc&7;
    int t = threadIdx.x;
    float s = bc1[c];
    #pragma unroll
    for(int jj=0;jj<32;jj++)
        s += g_z1p[(((jj*16+b)*8+c)<<8) + t];
    g_z1[bc*256 + t] = s;
    float p = s, q = s*s;
    #pragma unroll
    for(int o=16;o;o>>=1){
        p += __shfl_xor_sync(0xffffffffu, p, o);
        q += __shfl_xor_sync(0xffffffffu, q, o);
    }
    if((t&31)==0) sb[t>>5] = make_float2(p,q);
    __syncthreads();
    if(t==0){
        float P=0.f,Q=0.f;
        #pragma unroll
        for(int w=0;w<8;w++){ P+=sb[w].x; Q+=sb[w].y; }
        float m = P*(1.f/256.f);
        g_cm[bc]=m;
        g_cr[bc]=rsqrtf(Q*(1.f/256.f)-m*m+EPSV);
    }
}

// ---- K3: GN-apply + qkv + split-K attention partials; block=(b,h,chunk of 8) ----
__global__ void __launch_bounds__(256) k_attn(const float* __restrict__ ga,
                                              const float* __restrict__ ba,
                                              const float* __restrict__ wq,
                                              const float* __restrict__ bq){
    __shared__ float2 sk[256], sv[256];
    __shared__ float swq[192];
    int blk = blockIdx.x;              // b*32 + h*8 + chunk
    int b = blk>>5, h = (blk>>3)&3, ch = blk&7;
    int t = threadIdx.x;               // row
    if(t<192) swq[t] = wq[t];
    __syncthreads();
    float nv[8];
    #pragma unroll
    for(int c=0;c<8;c++){
        int bc = b*8+c;
        float z = g_z1[bc*256+t];
        nv[c] = (z-g_cm[bc])*g_cr[bc]*ga[c] + ba[c];
    }
    float q0=bq[2*h], q1=bq[2*h+1];
    float k0=bq[8+2*h], k1=bq[9+2*h];
    float v0=bq[16+2*h], v1=bq[17+2*h];
    #pragma unroll
    for(int c=0;c<8;c++){
        q0 += swq[(2*h  )*8+c]*nv[c];
        q1 += swq[(2*h+1)*8+c]*nv[c];
        k0 += swq[(8+2*h)*8+c]*nv[c];
        k1 += swq[(9+2*h)*8+c]*nv[c];
        v0 += swq[(16+2*h)*8+c]*nv[c];
        v1 += swq[(17+2*h)*8+c]*nv[c];
    }
    sk[t] = make_float2(k0,k1);
    sv[t] = make_float2(v0,v1);
    const float scale = 0.7071067811865475f;
    q0*=scale; q1*=scale;
    __syncthreads();
    float den=0.f, a0=0.f, a1=0.f;
    int m0 = ch*32;
    #pragma unroll 8
    for(int m=m0;m<m0+32;m++){          // broadcast LDS
        float2 kk = sk[m];
        float e = __expf(q0*kk.x + q1*kk.y);
        float2 vv = sv[m];
        den += e;
        a0 += e*vv.x; a1 += e*vv.y;
    }
    g_p4[blk*256 + t] = make_float4(den, a0, a1, 0.f);
}

// ---- K4: combine attn + proj+res + LN + MLP(gelu) + res -> z3 + GN2 partials ----
__global__ void __launch_bounds__(128) k_mlp(
        const float* __restrict__ wp, const float* __restrict__ bp,
        const float* __restrict__ lng, const float* __restrict__ lnb,
        const float* __restrict__ wf1, const float* __restrict__ bf1,
        const float* __restrict__ wf2, const float* __restrict__ bf2){
    __shared__ float sred[16*4];
    int b = blockIdx.x, chunk = blockIdx.y, t = threadIdx.x;
    int p = chunk*32 + (t>>2), sub = t&3;      // pixel, head-lane
    float den=0.f, s0=0.f, s1=0.f;
    #pragma unroll
    for(int ch=0;ch<8;ch++){
        float4 v = g_p4[((b*32 + sub*8 + ch)<<8) + p];
        den += v.x; s0 += v.y; s1 += v.z;
    }
    float inv = __fdividef(1.0f, den);
    float aoh0 = s0*inv, aoh1 = s1*inv;
    float ao[8];
    #pragma unroll
    for(int h=0;h<4;h++){
        ao[2*h]   = __shfl_sync(0xffffffffu, aoh0, h, 4);
        ao[2*h+1] = __shfl_sync(0xffffffffu, aoh1, h, 4);
    }
    float z2[8];
    #pragma unroll
    for(int c=0;c<8;c++){
        float s = bp[c] + g_z1[(b*8+c)*256+p];
        #pragma unroll
        for(int d=0;d<8;d++) s += wp[c*8+d]*ao[d];
        z2[c]=s;
    }
    float mu=0.f;
    #pragma unroll
    for(int c=0;c<8;c++) mu += z2[c];
    mu *= 0.125f;
    float var=0.f;
    #pragma unroll
    for(int c=0;c<8;c++){ float d=z2[c]-mu; var += d*d; }
    float rsl = rsqrtf(var*0.125f + EPSV);
    float ln[8];
    #pragma unroll
    for(int c=0;c<8;c++) ln[c] = (z2[c]-mu)*rsl*lng[c] + lnb[c];
    float hg[4];
    #pragma unroll
    for(int u=0;u<4;u++){
        int jj = sub*4+u;
        float s = bf1[jj];
        #pragma unroll
        for(int c=0;c<8;c++) s += wf1[jj*8+c]*ln[c];
        hg[u] = 0.5f*s*(1.0f + erff(s*0.7071067811865475f));
    }
    float z3[8];
    #pragma unroll
    for(int c=0;c<8;c++){
        float s = 0.f;
        #pragma unroll
        for(int u=0;u<4;u++) s += wf2[c*16 + sub*4+u]*hg[u];
        s += __shfl_xor_sync(0xffffffffu, s, 1);
        s += __shfl_xor_sync(0xffffffffu, s, 2);
        z3[c] = z2[c] + bf2[c] + s;
    }
    if(sub==0){
        #pragma unroll
        for(int c=0;c<8;c++) g_z3[(b*8+c)*256+p] = z3[c];
    }
    float red[16];
    #pragma unroll
    for(int c=0;c<8;c++){ red[c]=z3[c]; red[8+c]=z3[c]*z3[c]; }
    #pragma unroll
    for(int q=0;q<16;q++)
        #pragma unroll
        for(int o=16;o;o>>=1) red[q] += __shfl_xor_sync(0xffffffffu, red[q], o);
    if((t&31)==0){
        #pragma unroll
        for(int q=0;q<16;q++) sred[q*4 + (t>>5)] = red[q];
    }
    __syncthreads();
    if(t<16){
        float tot = sred[t*4]+sred[t*4+1]+sred[t*4+2]+sred[t*4+3];
        g_gs[(b*8+chunk)*16 + t] = tot;   // 4x each pixel -> /1024 later
    }
}

// ---- K5: GN2-apply + SiLU staging + upsample+conv2 (8->320), scalar FFMA ----
__global__ void __launch_bounds__(256) k_conv2(const float* __restrict__ bc2,
                                               const float* __restrict__ g2,
                                               const float* __restrict__ b2,
                                               float* __restrict__ out){
    __shared__ __align__(16) float sa[2592];   // padded silu(gn2) planes 8x18x18
    __shared__ __align__(16) float sw[1152];   // collapsed weights for 4 o-ch
    __shared__ float sst[16];
    int og = blockIdx.x, b = blockIdx.y;
    int t = threadIdx.x;
    {
        float4 z4 = make_float4(0.f,0.f,0.f,0.f);
        float4* sa4 = (float4*)sa;
        for(int i=t;i<648;i+=256) sa4[i] = z4;
    }
    {   // weights: straight vector copy from precomputed g_kw
        const float4* kw4 = (const float4*)(g_kw + og*1152);
        float4* sw4 = (float4*)sw;
        for(int i=t;i<288;i+=256) sw4[i] = kw4[i];
    }
    if(t<16){
        float tot=0.f;
        #pragma unroll
        for(int k=0;k<8;k++) tot += g_gs[(b*8+k)*16 + t];
        sst[t]=tot;
    }
    __syncthreads();
    {
        int Y=t>>4, X=t&15;
        #pragma unroll
        for(int c=0;c<8;c++){
            float m  = sst[c]*(1.f/1024.f);
            float rs = rsqrtf(sst[8+c]*(1.f/1024.f)-m*m+EPSV);
            float v = g_z3[(b*8+c)*256 + t];
            sa[c*324 + (Y+1)*18 + (X+1)] = siluf((v-m)*rs*g2[c] + b2[c]);
        }
    }
    __syncthreads();
    int ol = t>>6, u = t&63, Yq = u>>2, Xs = u&3;
    int o = og*4+ol;
    float bias = bc2[o];
    float acc[64];
    #pragma unroll
    for(int i=0;i<64;i++) acc[i]=bias;
    const int RYof[6]={3,0,1,2,3,0};
    const int RWof[6]={2,1,1,1,1,0};
    const int XL0[6] ={3,0,1,2,3,0};
    const int SCB[6] ={2,1,1,1,1,0};
    #pragma unroll
    for(int c=0;c<8;c++){
        float aw[3][6];
        #pragma unroll
        for(int r=0;r<3;r++){
            const float2* sar = (const float2*)&sa[(c*18 + Yq + r)*18 + 4*Xs];
            float2 p0=sar[0], p1=sar[1], p2=sar[2];
            aw[r][0]=p0.x; aw[r][1]=p0.y; aw[r][2]=p1.x;
            aw[r][3]=p1.y; aw[r][4]=p2.x; aw[r][5]=p2.y;
        }
        const float2* wc2 = (const float2*)&sw[(ol*8 + c)*36];
        #pragma unroll
        for(int ky=0;ky<6;ky++){
            int ry = RYof[ky], riw = RWof[ky];
            float2 wA = wc2[ky*3], wB = wc2[ky*3+1], wC = wc2[ky*3+2];
            float wv[6] = {wA.x, wA.y, wB.x, wB.y, wC.x, wC.y};
            #pragma unroll
            for(int kx=0;kx<6;kx++){
                float w = wv[kx];
                int xl0 = XL0[kx], scb = SCB[kx];
                #pragma unroll
                for(int j=0;j<4;j++)
                    acc[ry*16 + xl0 + 4*j] += w * aw[riw][scb + j];
            }
        }
    }
    float4* ob = (float4*)(out + ((size_t)(b*320 + o)*64 + 4*Yq)*64 + 16*Xs);
    #pragma unroll
    for(int ry=0;ry<4;ry++)
        #pragma unroll
        for(int j=0;j<4;j++)
            ob[ry*16 + j] = make_float4(acc[ry*16+j*4], acc[ry*16+j*4+1],
                                        acc[ry*16+j*4+2], acc[ry*16+j*4+3]);
}

extern "C" void kernel_launch(void* const* d_in, const int* in_sizes, int n_in,
                              void* d_out, int out_size) {
    const float* x   = (const float*)d_in[0];
    const float* g1  = (const float*)d_in[1];
    const float* b1  = (const float*)d_in[2];
    const float* w1  = (const float*)d_in[3];
    const float* bc1 = (const float*)d_in[4];
    const float* ga  = (const float*)d_in[5];
    const float* ba  = (const float*)d_in[6];
    const float* wq  = (const float*)d_in[7];
    const float* bq  = (const float*)d_in[8];
    const float* wp  = (const float*)d_in[9];
    const float* bp  = (const float*)d_in[10];
    const float* lng = (const float*)d_in[11];
    const float* lnb = (const float*)d_in[12];
    const float* wf1 = (const float*)d_in[13];
    const float* bf1 = (const float*)d_in[14];
    const float* wf2 = (const float*)d_in[15];
    const float* bf2 = (const float*)d_in[16];
    const float* g2  = (const float*)d_in[17];
    const float* b2  = (const float*)d_in[18];
    const float* w2  = (const float*)d_in[19];
    const float* bc2 = (const float*)d_in[20];
    float* out = (float*)d_out;

    k_pconv1<<<dim3(32,16), 256>>>(x, g1, b1, w1, w2);
    k_merge <<<128, 256>>>(bc1);
    k_attn  <<<512, 256>>>(ga, ba, wq, bq);
    k_mlp   <<<dim3(16,8), 128>>>(wp, bp, lng, lnb, wf1, bf1, wf2, bf2);
    k_conv2 <<<dim3(80,16), 256>>>(bc2, g2, b2, out);
}